// round 1
// baseline (speedup 1.0000x reference)
#include <cuda_runtime.h>
#include <cstdint>

#define NMAX 100000
#define DIM 64

// ---------------- scratch (static device globals; no allocation) ----------------
__device__ __align__(16) float g_agg[NMAX * DIM];    // aggregation buffer (reused both layers)
__device__ __align__(16) float g_h[NMAX * DIM];      // layer-1 output, pre-scaled by norm_out
__device__ int   g_deg_out[NMAX];
__device__ int   g_deg_in[NMAX];
__device__ float g_norm_out[NMAX];
__device__ float g_norm_in[NMAX];

// ---------------- zero / init ----------------
__global__ void zero_init_kernel(int n_nodes) {
    int i = blockIdx.x * blockDim.x + threadIdx.x;
    int tot = n_nodes * (DIM / 4);
    if (i < tot) reinterpret_cast<float4*>(g_agg)[i] = make_float4(0.f, 0.f, 0.f, 0.f);
    if (i < n_nodes) { g_deg_out[i] = 0; g_deg_in[i] = 0; }
}

__global__ void zero_agg_kernel(int n_nodes) {
    int i = blockIdx.x * blockDim.x + threadIdx.x;
    int tot = n_nodes * (DIM / 4);
    if (i < tot) reinterpret_cast<float4*>(g_agg)[i] = make_float4(0.f, 0.f, 0.f, 0.f);
}

// ---------------- degrees + norms ----------------
__global__ void degree_kernel(const int* __restrict__ src, const int* __restrict__ dst,
                              int n_edges) {
    int e = blockIdx.x * blockDim.x + threadIdx.x;
    if (e < n_edges) {
        atomicAdd(&g_deg_out[src[e]], 1);
        atomicAdd(&g_deg_in[dst[e]], 1);
    }
}

__global__ void norm_kernel(int n_nodes) {
    int i = blockIdx.x * blockDim.x + threadIdx.x;
    if (i < n_nodes) {
        g_norm_out[i] = rsqrtf(fmaxf((float)g_deg_out[i], 1.0f));
        g_norm_in[i]  = rsqrtf(fmaxf((float)g_deg_in[i],  1.0f));
    }
}

// ---------------- scatter-aggregate: agg[dst] += feat[src] (* norm_out[src] for layer 1) ----
// 16 threads per edge; each thread handles one float4 of the 64-float row.
// Vector atomic red.global.add.v4.f32 (sm_90+) quarters the atomic message count.
template <bool FIRST>
__global__ void __launch_bounds__(256) scatter_kernel(
    const float* __restrict__ feat,
    const int* __restrict__ src, const int* __restrict__ dst,
    int n_edges)
{
    int gid = blockIdx.x * blockDim.x + threadIdx.x;
    int e = gid >> 4;
    if (e >= n_edges) return;
    int q = gid & 15;

    int s = __ldg(src + e);
    int d = __ldg(dst + e);

    const float4* f4 = FIRST ? reinterpret_cast<const float4*>(feat)
                             : reinterpret_cast<const float4*>(g_h);
    float4 v = __ldg(f4 + (size_t)s * 16 + q);
    if (FIRST) {
        float sc = __ldg(&g_norm_out[s]);
        v.x *= sc; v.y *= sc; v.z *= sc; v.w *= sc;
    }
    float* p = g_agg + (size_t)d * DIM + q * 4;
    asm volatile("red.global.add.v4.f32 [%0], {%1, %2, %3, %4};"
                 :: "l"(p), "f"(v.x), "f"(v.y), "f"(v.z), "f"(v.w)
                 : "memory");
}

// ---------------- dense: out = act((agg * norm_in) @ W + b) [* norm_out if RELU_SCALE] ----
// Tile: 96 nodes per block, 192 threads = 16 col-groups x 12 node-groups,
// each thread computes 8 nodes x 4 cols (32 fp32 accumulators).
// W staged in smem (float4 reads), A tile staged with +1 padding (conflict-free scalar reads).
template <bool RELU_SCALE>
__global__ void __launch_bounds__(192) dense_kernel(
    const float* __restrict__ W, const float* __restrict__ bias,
    float* __restrict__ out, int n_nodes)
{
    __shared__ float sW[DIM * DIM];       // 16 KB
    __shared__ float sb[DIM];
    __shared__ float sA[96][DIM + 1];     // ~25 KB, padded

    int tid = threadIdx.x;

    for (int i = tid; i < DIM * DIM / 4; i += 192)
        reinterpret_cast<float4*>(sW)[i] = reinterpret_cast<const float4*>(W)[i];
    if (tid < DIM / 4)
        reinterpret_cast<float4*>(sb)[tid] = reinterpret_cast<const float4*>(bias)[tid];

    int node0 = blockIdx.x * 96;

    // stage A tile, fused with norm_in scaling
    for (int i = tid; i < 96 * 16; i += 192) {
        int r = i >> 4, q = i & 15;
        int node = node0 + r;
        float4 v = make_float4(0.f, 0.f, 0.f, 0.f);
        float ni = 0.f;
        if (node < n_nodes) {
            v  = reinterpret_cast<const float4*>(g_agg)[(size_t)node * 16 + q];
            ni = g_norm_in[node];
        }
        sA[r][q * 4 + 0] = v.x * ni;
        sA[r][q * 4 + 1] = v.y * ni;
        sA[r][q * 4 + 2] = v.z * ni;
        sA[r][q * 4 + 3] = v.w * ni;
    }
    __syncthreads();

    int cg = tid & 15;        // column group: cols cg*4 .. cg*4+3
    int ng = tid >> 4;        // node group:   nodes ng*8 .. ng*8+7

    float4 acc[8];
#pragma unroll
    for (int i = 0; i < 8; i++) acc[i] = make_float4(0.f, 0.f, 0.f, 0.f);

    const float4* sW4 = reinterpret_cast<const float4*>(sW);
#pragma unroll 8
    for (int k = 0; k < DIM; k++) {
        float4 w = sW4[k * 16 + cg];
#pragma unroll
        for (int i = 0; i < 8; i++) {
            float a = sA[ng * 8 + i][k];
            acc[i].x = fmaf(a, w.x, acc[i].x);
            acc[i].y = fmaf(a, w.y, acc[i].y);
            acc[i].z = fmaf(a, w.z, acc[i].z);
            acc[i].w = fmaf(a, w.w, acc[i].w);
        }
    }

    float4 bb = reinterpret_cast<const float4*>(sb)[cg];
#pragma unroll
    for (int i = 0; i < 8; i++) {
        int node = node0 + ng * 8 + i;
        if (node >= n_nodes) break;
        float4 y;
        y.x = acc[i].x + bb.x;
        y.y = acc[i].y + bb.y;
        y.z = acc[i].z + bb.z;
        y.w = acc[i].w + bb.w;
        if (RELU_SCALE) {
            // fuse relu and next layer's source-side norm into the store
            float sc = g_norm_out[node];
            y.x = fmaxf(y.x, 0.f) * sc;
            y.y = fmaxf(y.y, 0.f) * sc;
            y.z = fmaxf(y.z, 0.f) * sc;
            y.w = fmaxf(y.w, 0.f) * sc;
            reinterpret_cast<float4*>(g_h)[(size_t)node * 16 + cg] = y;
        } else {
            reinterpret_cast<float4*>(out)[(size_t)node * 16 + cg] = y;
        }
    }
}

// ---------------- launch ----------------
extern "C" void kernel_launch(void* const* d_in, const int* in_sizes, int n_in,
                              void* d_out, int out_size)
{
    const int*   src = (const int*)d_in[0];
    const int*   dst = (const int*)d_in[1];
    const float* x   = (const float*)d_in[2];
    const float* W1  = (const float*)d_in[3];
    const float* b1  = (const float*)d_in[4];
    const float* W2  = (const float*)d_in[5];
    const float* b2  = (const float*)d_in[6];

    int E = in_sizes[0];
    int N = in_sizes[2] / DIM;
    if (N > NMAX) N = NMAX;

    int zthreads = N * 16;
    long long sthreads = (long long)E * 16;

    zero_init_kernel<<<(zthreads + 255) / 256, 256>>>(N);
    degree_kernel<<<(E + 255) / 256, 256>>>(src, dst, E);
    norm_kernel<<<(N + 255) / 256, 256>>>(N);

    scatter_kernel<true><<<(int)((sthreads + 255) / 256), 256>>>(x, src, dst, E);
    dense_kernel<true><<<(N + 95) / 96, 192>>>(W1, b1, nullptr, N);

    zero_agg_kernel<<<(zthreads + 255) / 256, 256>>>(N);
    scatter_kernel<false><<<(int)((sthreads + 255) / 256), 256>>>(nullptr, src, dst, E);
    dense_kernel<false><<<(N + 95) / 96, 192>>>(W2, b2, (float*)d_out, N);
}

// round 3
// speedup vs baseline: 1.2438x; 1.2438x over previous
#include <cuda_runtime.h>
#include <cstdint>

#define NMAX 100000
#define EMAX 1000000
#define DIM 64

// ---------------- scratch (static device globals; no allocation) ----------------
__device__ __align__(16) float g_agg[NMAX * DIM];    // aggregation buffer (reused both layers)
__device__ __align__(16) float g_h[NMAX * DIM];      // layer-1 output, pre-scaled by norm_out
__device__ int   g_deg_out[NMAX];
__device__ int   g_deg_in[NMAX];
__device__ float g_norm_out[NMAX];
__device__ float g_norm_in[NMAX];
// CSR by destination
__device__ int   g_row_start[NMAX];
__device__ int   g_cursor[NMAX];
__device__ int   g_esrc[EMAX];
__device__ int   g_block_sums[256];

// ---------------- init ----------------
__global__ void zero_deg_kernel(int n_nodes) {
    int i = blockIdx.x * blockDim.x + threadIdx.x;
    if (i < n_nodes) { g_deg_out[i] = 0; g_deg_in[i] = 0; }
}

__global__ void degree_kernel(const int* __restrict__ src, const int* __restrict__ dst,
                              int n_edges) {
    int e = blockIdx.x * blockDim.x + threadIdx.x;
    if (e < n_edges) {
        atomicAdd(&g_deg_out[src[e]], 1);
        atomicAdd(&g_deg_in[dst[e]], 1);
    }
}

__global__ void norm_kernel(int n_nodes) {
    int i = blockIdx.x * blockDim.x + threadIdx.x;
    if (i < n_nodes) {
        g_norm_out[i] = rsqrtf(fmaxf((float)g_deg_out[i], 1.0f));
        g_norm_in[i]  = rsqrtf(fmaxf((float)g_deg_in[i],  1.0f));
    }
}

// ---------------- CSR build: block sums -> scan+fill starts -> cursor fill ------
__global__ void __launch_bounds__(256) blocksum_kernel(int n_nodes) {
    int base = blockIdx.x * 1024;
    int t = threadIdx.x;
    int local = 0;
#pragma unroll
    for (int j = 0; j < 4; j++) {
        int idx = base + t * 4 + j;
        if (idx < n_nodes) local += g_deg_in[idx];
    }
    for (int o = 16; o > 0; o >>= 1) local += __shfl_down_sync(~0u, local, o);
    __shared__ int ws[8];
    if ((t & 31) == 0) ws[t >> 5] = local;
    __syncthreads();
    if (t == 0) {
        int s = 0;
#pragma unroll
        for (int w = 0; w < 8; w++) s += ws[w];
        g_block_sums[blockIdx.x] = s;
    }
}

__global__ void __launch_bounds__(256) scanfill_kernel(int n_nodes, int n_blocks) {
    int t = threadIdx.x;
    int bid = blockIdx.x;

    // block offset = sum of earlier block sums
    int v = (t < bid && t < n_blocks) ? g_block_sums[t] : 0;
    for (int o = 16; o > 0; o >>= 1) v += __shfl_down_sync(~0u, v, o);
    __shared__ int ws[8];
    __shared__ int s_off;
    if ((t & 31) == 0) ws[t >> 5] = v;
    __syncthreads();
    if (t == 0) {
        int s = 0;
#pragma unroll
        for (int w = 0; w < 8; w++) s += ws[w];
        s_off = s;
    }
    __syncthreads();
    int block_off = s_off;

    int base = bid * 1024;
    int d[4]; int local = 0;
#pragma unroll
    for (int j = 0; j < 4; j++) {
        int idx = base + t * 4 + j;
        d[j] = (idx < n_nodes) ? g_deg_in[idx] : 0;
        local += d[j];
    }
    int lane = t & 31, w = t >> 5;
    int s = local;
    for (int o = 1; o < 32; o <<= 1) {
        int x = __shfl_up_sync(~0u, s, o);
        if (lane >= o) s += x;
    }
    __shared__ int wsum[8];
    if (lane == 31) wsum[w] = s;
    __syncthreads();
    if (w == 0 && lane < 8) {
        int x = wsum[lane];
        for (int o = 1; o < 8; o <<= 1) {
            int y = __shfl_up_sync(0xffu, x, o);
            if (lane >= o) x += y;
        }
        wsum[lane] = x;
    }
    __syncthreads();
    int excl = s - local + (w > 0 ? wsum[w - 1] : 0) + block_off;
#pragma unroll
    for (int j = 0; j < 4; j++) {
        int idx = base + t * 4 + j;
        if (idx < n_nodes) { g_row_start[idx] = excl; g_cursor[idx] = excl; }
        excl += d[j];
    }
}

__global__ void csrfill_kernel(const int* __restrict__ src, const int* __restrict__ dst,
                               int n_edges) {
    int e = blockIdx.x * blockDim.x + threadIdx.x;
    if (e < n_edges) {
        int pos = atomicAdd(&g_cursor[dst[e]], 1);
        g_esrc[pos] = src[e];
    }
}

// ---------------- pull-mode gather: agg[n] = norm_in[n] * sum_{e: dst=n} feat[src_e] ----
// 16 lanes per node (one float4 each), no atomics. MLP=4 in the main loop to
// cover the ~234cyc L2-hit latency at average in-degree ~10.
template <bool FIRST>
__global__ void __launch_bounds__(256) gather_kernel(
    const float* __restrict__ feat, int n_nodes)
{
    int gid = blockIdx.x * blockDim.x + threadIdx.x;
    int node = gid >> 4;
    if (node >= n_nodes) return;
    int q = gid & 15;

    const float4* f4 = FIRST ? reinterpret_cast<const float4*>(feat)
                             : reinterpret_cast<const float4*>(g_h);

    int beg = __ldg(&g_row_start[node]);
    int end = beg + __ldg(&g_deg_in[node]);

    float4 a0 = make_float4(0.f, 0.f, 0.f, 0.f);
    float4 a1 = make_float4(0.f, 0.f, 0.f, 0.f);
    float4 a2 = make_float4(0.f, 0.f, 0.f, 0.f);
    float4 a3 = make_float4(0.f, 0.f, 0.f, 0.f);

    int i = beg;
    for (; i + 4 <= end; i += 4) {
        int s0 = __ldg(&g_esrc[i]);
        int s1 = __ldg(&g_esrc[i + 1]);
        int s2 = __ldg(&g_esrc[i + 2]);
        int s3 = __ldg(&g_esrc[i + 3]);
        float4 v0 = __ldg(f4 + (size_t)s0 * 16 + q);
        float4 v1 = __ldg(f4 + (size_t)s1 * 16 + q);
        float4 v2 = __ldg(f4 + (size_t)s2 * 16 + q);
        float4 v3 = __ldg(f4 + (size_t)s3 * 16 + q);
        if (FIRST) {
            float n0 = __ldg(&g_norm_out[s0]);
            float n1 = __ldg(&g_norm_out[s1]);
            float n2 = __ldg(&g_norm_out[s2]);
            float n3 = __ldg(&g_norm_out[s3]);
            v0.x *= n0; v0.y *= n0; v0.z *= n0; v0.w *= n0;
            v1.x *= n1; v1.y *= n1; v1.z *= n1; v1.w *= n1;
            v2.x *= n2; v2.y *= n2; v2.z *= n2; v2.w *= n2;
            v3.x *= n3; v3.y *= n3; v3.z *= n3; v3.w *= n3;
        }
        a0.x += v0.x; a0.y += v0.y; a0.z += v0.z; a0.w += v0.w;
        a1.x += v1.x; a1.y += v1.y; a1.z += v1.z; a1.w += v1.w;
        a2.x += v2.x; a2.y += v2.y; a2.z += v2.z; a2.w += v2.w;
        a3.x += v3.x; a3.y += v3.y; a3.z += v3.z; a3.w += v3.w;
    }
    for (; i < end; i++) {
        int s0 = __ldg(&g_esrc[i]);
        float4 v0 = __ldg(f4 + (size_t)s0 * 16 + q);
        if (FIRST) {
            float n0 = __ldg(&g_norm_out[s0]);
            v0.x *= n0; v0.y *= n0; v0.z *= n0; v0.w *= n0;
        }
        a0.x += v0.x; a0.y += v0.y; a0.z += v0.z; a0.w += v0.w;
    }

    float ni = __ldg(&g_norm_in[node]);
    float4 r;
    r.x = (a0.x + a1.x + a2.x + a3.x) * ni;
    r.y = (a0.y + a1.y + a2.y + a3.y) * ni;
    r.z = (a0.z + a1.z + a2.z + a3.z) * ni;
    r.w = (a0.w + a1.w + a2.w + a3.w) * ni;
    reinterpret_cast<float4*>(g_agg)[(size_t)node * 16 + q] = r;
}

// ---------------- dense: out = act(agg @ W + b) [* norm_out if RELU_SCALE] ----
template <bool RELU_SCALE>
__global__ void __launch_bounds__(192) dense_kernel(
    const float* __restrict__ W, const float* __restrict__ bias,
    float* __restrict__ out, int n_nodes)
{
    __shared__ float sW[DIM * DIM];
    __shared__ float sb[DIM];
    __shared__ float sA[96][DIM + 1];

    int tid = threadIdx.x;

    for (int i = tid; i < DIM * DIM / 4; i += 192)
        reinterpret_cast<float4*>(sW)[i] = reinterpret_cast<const float4*>(W)[i];
    if (tid < DIM / 4)
        reinterpret_cast<float4*>(sb)[tid] = reinterpret_cast<const float4*>(bias)[tid];

    int node0 = blockIdx.x * 96;

    for (int i = tid; i < 96 * 16; i += 192) {
        int r = i >> 4, q = i & 15;
        int node = node0 + r;
        float4 v = make_float4(0.f, 0.f, 0.f, 0.f);
        if (node < n_nodes)
            v = reinterpret_cast<const float4*>(g_agg)[(size_t)node * 16 + q];
        sA[r][q * 4 + 0] = v.x;
        sA[r][q * 4 + 1] = v.y;
        sA[r][q * 4 + 2] = v.z;
        sA[r][q * 4 + 3] = v.w;
    }
    __syncthreads();

    int cg = tid & 15;
    int ng = tid >> 4;

    float4 acc[8];
#pragma unroll
    for (int i = 0; i < 8; i++) acc[i] = make_float4(0.f, 0.f, 0.f, 0.f);

    const float4* sW4 = reinterpret_cast<const float4*>(sW);
#pragma unroll 8
    for (int k = 0; k < DIM; k++) {
        float4 w = sW4[k * 16 + cg];
#pragma unroll
        for (int i = 0; i < 8; i++) {
            float a = sA[ng * 8 + i][k];
            acc[i].x = fmaf(a, w.x, acc[i].x);
            acc[i].y = fmaf(a, w.y, acc[i].y);
            acc[i].z = fmaf(a, w.z, acc[i].z);
            acc[i].w = fmaf(a, w.w, acc[i].w);
        }
    }

    float4 bb = reinterpret_cast<const float4*>(sb)[cg];
#pragma unroll
    for (int i = 0; i < 8; i++) {
        int node = node0 + ng * 8 + i;
        if (node >= n_nodes) break;
        float4 y;
        y.x = acc[i].x + bb.x;
        y.y = acc[i].y + bb.y;
        y.z = acc[i].z + bb.z;
        y.w = acc[i].w + bb.w;
        if (RELU_SCALE) {
            float sc = g_norm_out[node];
            y.x = fmaxf(y.x, 0.f) * sc;
            y.y = fmaxf(y.y, 0.f) * sc;
            y.z = fmaxf(y.z, 0.f) * sc;
            y.w = fmaxf(y.w, 0.f) * sc;
            reinterpret_cast<float4*>(g_h)[(size_t)node * 16 + cg] = y;
        } else {
            reinterpret_cast<float4*>(out)[(size_t)node * 16 + cg] = y;
        }
    }
}

// ---------------- launch ----------------
extern "C" void kernel_launch(void* const* d_in, const int* in_sizes, int n_in,
                              void* d_out, int out_size)
{
    const int*   src = (const int*)d_in[0];
    const int*   dst = (const int*)d_in[1];
    const float* x   = (const float*)d_in[2];
    const float* W1  = (const float*)d_in[3];
    const float* b1  = (const float*)d_in[4];
    const float* W2  = (const float*)d_in[5];
    const float* b2  = (const float*)d_in[6];

    int E = in_sizes[0];
    int N = in_sizes[2] / DIM;
    if (N > NMAX) N = NMAX;
    if (E > EMAX) E = EMAX;

    int n_scan_blocks = (N + 1023) / 1024;
    int gthreads = N * 16;

    zero_deg_kernel<<<(N + 255) / 256, 256>>>(N);
    degree_kernel<<<(E + 255) / 256, 256>>>(src, dst, E);
    norm_kernel<<<(N + 255) / 256, 256>>>(N);

    blocksum_kernel<<<n_scan_blocks, 256>>>(N);
    scanfill_kernel<<<n_scan_blocks, 256>>>(N, n_scan_blocks);
    csrfill_kernel<<<(E + 255) / 256, 256>>>(src, dst, E);

    gather_kernel<true><<<(gthreads + 255) / 256, 256>>>(x, N);
    dense_kernel<true><<<(N + 95) / 96, 192>>>(W1, b1, nullptr, N);

    gather_kernel<false><<<(gthreads + 255) / 256, 256>>>(nullptr, N);
    dense_kernel<false><<<(N + 95) / 96, 192>>>(W2, b2, (float*)d_out, N);
}

// round 4
// speedup vs baseline: 1.3474x; 1.0833x over previous
#include <cuda_runtime.h>
#include <cstdint>

#define NMAX 100000
#define EMAX 1000000
#define DIM 64

// ---------------- scratch (static device globals; no allocation) ----------------
__device__ __align__(16) float g_h[NMAX * DIM];      // layer-1 output, pre-scaled by norm_out
__device__ int   g_deg_out[NMAX];
__device__ int   g_deg_in[NMAX];
__device__ float g_norm_out[NMAX];
__device__ float g_norm_in[NMAX];
__device__ int   g_row_start[NMAX];
__device__ int   g_cursor[NMAX];
__device__ int   g_esrc[EMAX];
__device__ int   g_total;

// ---------------- K1: zero degree counters + global cursor ----------------
__global__ void zero_deg_kernel(int n_nodes) {
    int i = blockIdx.x * blockDim.x + threadIdx.x;
    if (i < n_nodes) { g_deg_out[i] = 0; g_deg_in[i] = 0; }
    if (i == 0) g_total = 0;
}

// ---------------- K2: degree histogram ----------------
__global__ void degree_kernel(const int* __restrict__ src, const int* __restrict__ dst,
                              int n_edges) {
    int e = blockIdx.x * blockDim.x + threadIdx.x;
    if (e < n_edges) {
        atomicAdd(&g_deg_out[src[e]], 1);
        atomicAdd(&g_deg_in[dst[e]], 1);
    }
}

// ---------------- K3: block-scan row allocation (order-free) + norms ----------
// Each block scans 1024 deg_in values, claims a contiguous region of g_esrc via
// ONE atomicAdd on g_total, writes row_start/cursor, and computes both norms.
__global__ void __launch_bounds__(256) rowalloc_kernel(int n_nodes) {
    int t = threadIdx.x;
    int base = blockIdx.x * 1024;

    int d[4]; int local = 0;
#pragma unroll
    for (int j = 0; j < 4; j++) {
        int idx = base + t * 4 + j;
        d[j] = (idx < n_nodes) ? g_deg_in[idx] : 0;
        local += d[j];
    }
    int lane = t & 31, w = t >> 5;
    // warp inclusive scan
    int s = local;
    for (int o = 1; o < 32; o <<= 1) {
        int x = __shfl_up_sync(~0u, s, o);
        if (lane >= o) s += x;
    }
    __shared__ int wsum[8];
    __shared__ int s_off;
    if (lane == 31) wsum[w] = s;
    __syncthreads();
    if (w == 0 && lane < 8) {
        int x = wsum[lane];
        for (int o = 1; o < 8; o <<= 1) {
            int y = __shfl_up_sync(0xffu, x, o);
            if (lane >= o) x += y;
        }
        wsum[lane] = x;
    }
    __syncthreads();
    if (t == 0) s_off = atomicAdd(&g_total, wsum[7]);   // block's region base
    __syncthreads();

    int excl = s - local + (w > 0 ? wsum[w - 1] : 0) + s_off;
#pragma unroll
    for (int j = 0; j < 4; j++) {
        int idx = base + t * 4 + j;
        if (idx < n_nodes) {
            g_row_start[idx] = excl;
            g_cursor[idx]    = excl;
            g_norm_in[idx]   = rsqrtf(fmaxf((float)d[j], 1.0f));
            g_norm_out[idx]  = rsqrtf(fmaxf((float)g_deg_out[idx], 1.0f));
        }
        excl += d[j];
    }
}

// ---------------- K4: scatter edge sources into dst buckets ----------------
__global__ void csrfill_kernel(const int* __restrict__ src, const int* __restrict__ dst,
                               int n_edges) {
    int e = blockIdx.x * blockDim.x + threadIdx.x;
    if (e < n_edges) {
        int pos = atomicAdd(&g_cursor[dst[e]], 1);
        g_esrc[pos] = src[e];
    }
}

// ---------------- K5/K6: fused gather + dense layer -----------------------
// Per block: gather 96 node rows directly into sA (with norm_in applied),
// then out = act(sA @ W + b).
// FIRST:  feat = x (apply norm_out[src] per edge); epilogue relu*norm_out -> g_h
// !FIRST: feat = g_h (pre-scaled);                 epilogue + b -> out
template <bool FIRST>
__global__ void __launch_bounds__(192) fused_layer_kernel(
    const float* __restrict__ feat,
    const float* __restrict__ W, const float* __restrict__ bias,
    float* __restrict__ out, int n_nodes)
{
    __shared__ float sW[DIM * DIM];       // 16 KB
    __shared__ float sb[DIM];
    __shared__ float sA[96][DIM + 1];     // ~25 KB

    int tid = threadIdx.x;

    // stage W and bias (overlaps with gather loads below)
    for (int i = tid; i < DIM * DIM / 4; i += 192)
        reinterpret_cast<float4*>(sW)[i] = reinterpret_cast<const float4*>(W)[i];
    if (tid < DIM / 4)
        reinterpret_cast<float4*>(sb)[tid] = reinterpret_cast<const float4*>(bias)[tid];

    int node0 = blockIdx.x * 96;
    const float4* f4 = FIRST ? reinterpret_cast<const float4*>(feat)
                             : reinterpret_cast<const float4*>(g_h);

    // ---- gather stage: 1536 (node, quad) tasks over 192 threads ----
    for (int i = tid; i < 96 * 16; i += 192) {
        int r = i >> 4, q = i & 15;
        int node = node0 + r;
        float4 a0 = make_float4(0.f, 0.f, 0.f, 0.f);
        float4 a1 = make_float4(0.f, 0.f, 0.f, 0.f);
        float4 a2 = make_float4(0.f, 0.f, 0.f, 0.f);
        float4 a3 = make_float4(0.f, 0.f, 0.f, 0.f);
        float ni = 0.f;
        if (node < n_nodes) {
            ni = __ldg(&g_norm_in[node]);
            int beg = __ldg(&g_row_start[node]);
            int end = beg + __ldg(&g_deg_in[node]);
            int e = beg;
            for (; e + 4 <= end; e += 4) {
                int s0 = __ldg(&g_esrc[e]);
                int s1 = __ldg(&g_esrc[e + 1]);
                int s2 = __ldg(&g_esrc[e + 2]);
                int s3 = __ldg(&g_esrc[e + 3]);
                float4 v0 = __ldg(f4 + (size_t)s0 * 16 + q);
                float4 v1 = __ldg(f4 + (size_t)s1 * 16 + q);
                float4 v2 = __ldg(f4 + (size_t)s2 * 16 + q);
                float4 v3 = __ldg(f4 + (size_t)s3 * 16 + q);
                if (FIRST) {
                    float n0 = __ldg(&g_norm_out[s0]);
                    float n1 = __ldg(&g_norm_out[s1]);
                    float n2 = __ldg(&g_norm_out[s2]);
                    float n3 = __ldg(&g_norm_out[s3]);
                    v0.x *= n0; v0.y *= n0; v0.z *= n0; v0.w *= n0;
                    v1.x *= n1; v1.y *= n1; v1.z *= n1; v1.w *= n1;
                    v2.x *= n2; v2.y *= n2; v2.z *= n2; v2.w *= n2;
                    v3.x *= n3; v3.y *= n3; v3.z *= n3; v3.w *= n3;
                }
                a0.x += v0.x; a0.y += v0.y; a0.z += v0.z; a0.w += v0.w;
                a1.x += v1.x; a1.y += v1.y; a1.z += v1.z; a1.w += v1.w;
                a2.x += v2.x; a2.y += v2.y; a2.z += v2.z; a2.w += v2.w;
                a3.x += v3.x; a3.y += v3.y; a3.z += v3.z; a3.w += v3.w;
            }
            for (; e < end; e++) {
                int s0 = __ldg(&g_esrc[e]);
                float4 v0 = __ldg(f4 + (size_t)s0 * 16 + q);
                if (FIRST) {
                    float n0 = __ldg(&g_norm_out[s0]);
                    v0.x *= n0; v0.y *= n0; v0.z *= n0; v0.w *= n0;
                }
                a0.x += v0.x; a0.y += v0.y; a0.z += v0.z; a0.w += v0.w;
            }
        }
        sA[r][q * 4 + 0] = (a0.x + a1.x + a2.x + a3.x) * ni;
        sA[r][q * 4 + 1] = (a0.y + a1.y + a2.y + a3.y) * ni;
        sA[r][q * 4 + 2] = (a0.z + a1.z + a2.z + a3.z) * ni;
        sA[r][q * 4 + 3] = (a0.w + a1.w + a2.w + a3.w) * ni;
    }
    __syncthreads();

    // ---- dense stage: each thread 8 nodes x 4 cols ----
    int cg = tid & 15;
    int ng = tid >> 4;

    float4 acc[8];
#pragma unroll
    for (int i = 0; i < 8; i++) acc[i] = make_float4(0.f, 0.f, 0.f, 0.f);

    const float4* sW4 = reinterpret_cast<const float4*>(sW);
#pragma unroll 8
    for (int k = 0; k < DIM; k++) {
        float4 w = sW4[k * 16 + cg];
#pragma unroll
        for (int i = 0; i < 8; i++) {
            float a = sA[ng * 8 + i][k];
            acc[i].x = fmaf(a, w.x, acc[i].x);
            acc[i].y = fmaf(a, w.y, acc[i].y);
            acc[i].z = fmaf(a, w.z, acc[i].z);
            acc[i].w = fmaf(a, w.w, acc[i].w);
        }
    }

    float4 bb = reinterpret_cast<const float4*>(sb)[cg];
#pragma unroll
    for (int i = 0; i < 8; i++) {
        int node = node0 + ng * 8 + i;
        if (node >= n_nodes) break;
        float4 y;
        y.x = acc[i].x + bb.x;
        y.y = acc[i].y + bb.y;
        y.z = acc[i].z + bb.z;
        y.w = acc[i].w + bb.w;
        if (FIRST) {
            float sc = g_norm_out[node];   // pre-scale for layer-2 gather
            y.x = fmaxf(y.x, 0.f) * sc;
            y.y = fmaxf(y.y, 0.f) * sc;
            y.z = fmaxf(y.z, 0.f) * sc;
            y.w = fmaxf(y.w, 0.f) * sc;
            reinterpret_cast<float4*>(g_h)[(size_t)node * 16 + cg] = y;
        } else {
            reinterpret_cast<float4*>(out)[(size_t)node * 16 + cg] = y;
        }
    }
}

// ---------------- launch ----------------
extern "C" void kernel_launch(void* const* d_in, const int* in_sizes, int n_in,
                              void* d_out, int out_size)
{
    const int*   src = (const int*)d_in[0];
    const int*   dst = (const int*)d_in[1];
    const float* x   = (const float*)d_in[2];
    const float* W1  = (const float*)d_in[3];
    const float* b1  = (const float*)d_in[4];
    const float* W2  = (const float*)d_in[5];
    const float* b2  = (const float*)d_in[6];

    int E = in_sizes[0];
    int N = in_sizes[2] / DIM;
    if (N > NMAX) N = NMAX;
    if (E > EMAX) E = EMAX;

    zero_deg_kernel<<<(N + 255) / 256, 256>>>(N);
    degree_kernel<<<(E + 255) / 256, 256>>>(src, dst, E);
    rowalloc_kernel<<<(N + 1023) / 1024, 256>>>(N);
    csrfill_kernel<<<(E + 255) / 256, 256>>>(src, dst, E);

    fused_layer_kernel<true><<<(N + 95) / 96, 192>>>(x, W1, b1, nullptr, N);
    fused_layer_kernel<false><<<(N + 95) / 96, 192>>>(nullptr, W2, b2, (float*)d_out, N);
}